// round 15
// baseline (speedup 1.0000x reference)
#include <cuda_runtime.h>
#include <cuda_fp16.h>
#include <cstdint>

// Problem constants
#define BSZ    2
#define LSEQ   1024
#define DMODEL 1024
#define NH     16
#define DH     64
#define WWIN   64
#define MTOT   (BSZ * LSEQ)      // 2048

// ---------------------------------------------------------------------------
// Scratch (device globals — no allocation allowed)
// ---------------------------------------------------------------------------
__device__ __half g_xh  [MTOT * DMODEL];         // x -> fp16
__device__ __half g_wh  [3 * DMODEL * DMODEL];   // Wq|Wk|Wv rows stacked, fp16
__device__ __half g_woh [DMODEL * DMODEL];       // Wo fp16
__device__ __half g_atth[MTOT * DMODEL];         // attention out, fp16
__device__ float  g_qkv [MTOT * 3 * DMODEL];     // q|k|v f32, row-concat

// ---------------------------------------------------------------------------
// helpers
// ---------------------------------------------------------------------------
__device__ __forceinline__ uint32_t smem_u32(const void* p) {
    uint32_t a;
    asm("{ .reg .u64 t; cvta.to.shared.u64 t, %1; cvt.u32.u64 %0, t; }" : "=r"(a) : "l"(p));
    return a;
}
__device__ __forceinline__ float tf32_round(float v) {
    uint32_t o;
    asm("cvt.rna.tf32.f32 %0, %1;" : "=r"(o) : "f"(v));
    return __uint_as_float(o);
}
#define CP_ASYNC16(dst, src) \
    asm volatile("cp.async.cg.shared.global [%0], [%1], 16;" :: "r"(dst), "l"(src) : "memory")
#define CP_ASYNC_COMMIT() asm volatile("cp.async.commit_group;" ::: "memory")
#define CP_ASYNC_WAIT(n)  asm volatile("cp.async.wait_group %0;" :: "n"(n) : "memory")

__device__ __forceinline__ void mma_fp16(float* c, uint32_t a0, uint32_t a1,
                                         uint32_t a2, uint32_t a3,
                                         uint32_t b0, uint32_t b1) {
    asm volatile(
        "mma.sync.aligned.m16n8k16.row.col.f32.f16.f16.f32 "
        "{%0,%1,%2,%3}, {%4,%5,%6,%7}, {%8,%9}, {%0,%1,%2,%3};"
        : "+f"(c[0]), "+f"(c[1]), "+f"(c[2]), "+f"(c[3])
        : "r"(a0), "r"(a1), "r"(a2), "r"(a3), "r"(b0), "r"(b1));
}
__device__ __forceinline__ void mma_tf32(float* c, uint32_t a0, uint32_t a1,
                                         uint32_t a2, uint32_t a3,
                                         uint32_t b0, uint32_t b1) {
    asm volatile(
        "mma.sync.aligned.m16n8k8.row.col.f32.tf32.tf32.f32 "
        "{%0,%1,%2,%3}, {%4,%5,%6,%7}, {%8,%9}, {%0,%1,%2,%3};"
        : "+f"(c[0]), "+f"(c[1]), "+f"(c[2]), "+f"(c[3])
        : "r"(a0), "r"(a1), "r"(a2), "r"(a3), "r"(b0), "r"(b1));
}
__device__ __forceinline__ void ldsm4(uint32_t& r0, uint32_t& r1, uint32_t& r2,
                                      uint32_t& r3, uint32_t addr) {
    asm volatile("ldmatrix.sync.aligned.m8n8.x4.shared.b16 {%0,%1,%2,%3}, [%4];"
                 : "=r"(r0), "=r"(r1), "=r"(r2), "=r"(r3) : "r"(addr));
}

// ---------------------------------------------------------------------------
// FP16 tensor-core GEMM: C[M][Ntot](f32) = A[M][1024](fp16) @ B[Ntot][1024]^T
// CTA 128x128, BK=32 halves, 8 warps (64x32 warp tiles), 3-stage cp.async,
// ldmatrix fragments, mma.m16n8k16. 2 CTAs/SM.
// Row stride 80 B (= 5*16B aligned; 8-row ldmatrix phase covers all banks).
// ---------------------------------------------------------------------------
#define BK 32                          // halves per stage
#define NST (DMODEL / BK)              // 32 stages
#define SROWB 80                       // padded row, bytes (64 data + 16 pad)
#define TILEB (128 * SROWB)            // 10240 B per matrix per stage
#define STAGEB (2 * TILEB)             // 20480 B
#define GEMM_SMEM_BYTES (3 * STAGEB)   // 61440 B

__global__ __launch_bounds__(256, 2) void gemm_fp16_kernel(
    const __half* __restrict__ A, const __half* __restrict__ B,
    float* __restrict__ C, int Ntot)
{
    extern __shared__ char smem[];
    const int tid  = threadIdx.x;
    const int wid  = tid >> 5;
    const int lane = tid & 31;
    const int bn = blockIdx.x * 128;
    const int bm = blockIdx.y * 128;

    const int wm = (wid & 1) * 64;
    const int wn = (wid >> 1) * 32;
    const int qr = lane >> 2;
    const int qc = lane & 3;

    const uint32_t smem_base = smem_u32(smem);
    const __half* gA = A + (size_t)bm * DMODEL;
    const __half* gB = B + (size_t)bn * DMODEL;

    // ldmatrix lane maps (16B k-granules, same structure as validated tf32)
    const int a_row = ((lane >> 3) & 1) * 8 + (lane & 7);
    const int a_koB = (lane >> 4) * 16;           // k granule: 8 halves = 16B
    uint32_t offA[4];
    #pragma unroll
    for (int mi = 0; mi < 4; mi++)
        offA[mi] = (uint32_t)((wm + mi * 16 + a_row) * SROWB + a_koB);
    const int b_row = (lane >> 4) * 8 + (lane & 7);
    const int b_koB = ((lane >> 3) & 1) * 16;
    uint32_t offB[2];
    #pragma unroll
    for (int p = 0; p < 2; p++)
        offB[p] = (uint32_t)(TILEB + (wn + p * 16 + b_row) * SROWB + b_koB);

    auto load_stage = [&](int s) {
        uint32_t dst = smem_base + (uint32_t)(s % 3) * STAGEB;
        uint32_t dstB = dst + TILEB;
        const __half* pA = gA + s * BK;
        const __half* pB = gB + s * BK;
        #pragma unroll
        for (int i = 0; i < 2; i++) {
            int id = tid + i * 256;       // 0..511
            int row = id >> 2;            // 0..127
            int ch  = id & 3;             // 16B chunk (8 halves)
            uint32_t so = (uint32_t)(row * SROWB + ch * 16);
            CP_ASYNC16(dst  + so, pA + (size_t)row * DMODEL + ch * 8);
            CP_ASYNC16(dstB + so, pB + (size_t)row * DMODEL + ch * 8);
        }
    };

    float acc[4][4][4];
    #pragma unroll
    for (int mi = 0; mi < 4; mi++)
        #pragma unroll
        for (int ni = 0; ni < 4; ni++)
            #pragma unroll
            for (int j = 0; j < 4; j++) acc[mi][ni][j] = 0.0f;

    load_stage(0); CP_ASYNC_COMMIT();
    load_stage(1); CP_ASYNC_COMMIT();

    for (int s = 0; s < NST; s++) {
        CP_ASYNC_WAIT(1);
        __syncthreads();
        if (s + 2 < NST) load_stage(s + 2);
        CP_ASYNC_COMMIT();

        const uint32_t stage = smem_base + (uint32_t)(s % 3) * STAGEB;

        #pragma unroll
        for (int ks = 0; ks < 2; ks++) {              // 2 x k16 per BK=32
            const uint32_t kb = (uint32_t)(ks * 32);  // 16 halves = 32 B
            uint32_t af[4][4];
            #pragma unroll
            for (int mi = 0; mi < 4; mi++)
                ldsm4(af[mi][0], af[mi][1], af[mi][2], af[mi][3], stage + offA[mi] + kb);
            uint32_t bf[4][2];
            #pragma unroll
            for (int p = 0; p < 2; p++)
                ldsm4(bf[2*p][0], bf[2*p][1], bf[2*p+1][0], bf[2*p+1][1],
                      stage + offB[p] + kb);
            #pragma unroll
            for (int mi = 0; mi < 4; mi++)
                #pragma unroll
                for (int ni = 0; ni < 4; ni++)
                    mma_fp16(acc[mi][ni], af[mi][0], af[mi][1], af[mi][2], af[mi][3],
                             bf[ni][0], bf[ni][1]);
        }
    }

    #pragma unroll
    for (int mi = 0; mi < 4; mi++) {
        const int row = bm + wm + mi * 16 + qr;
        #pragma unroll
        for (int ni = 0; ni < 4; ni++) {
            const int col = bn + wn + ni * 8 + qc * 2;
            float* p0 = C + (size_t)row * Ntot + col;
            float* p1 = p0 + (size_t)8 * Ntot;
            *(float2*)p0 = make_float2(acc[mi][ni][0], acc[mi][ni][1]);
            *(float2*)p1 = make_float2(acc[mi][ni][2], acc[mi][ni][3]);
        }
    }
}

// ---------------------------------------------------------------------------
// Fused fp16 conversion prepass: x -> g_xh, Wq|Wk|Wv -> g_wh, Wo -> g_woh
// ---------------------------------------------------------------------------
#define XN4 (MTOT * DMODEL / 4)          // 524288
#define WN4 (DMODEL * DMODEL / 4)        // 262144
#define RN4 (XN4 + 4 * WN4)              // 1572864

__global__ __launch_bounds__(256) void round_all_kernel(
    const float* __restrict__ x,  const float* __restrict__ Wq,
    const float* __restrict__ Wk, const float* __restrict__ Wv,
    const float* __restrict__ Wo,
    __half* __restrict__ xh, __half* __restrict__ wh, __half* __restrict__ woh)
{
    int i = blockIdx.x * 256 + threadIdx.x;
    if (i >= RN4) return;
    const float4* src; __half* dst; int off;
    if (i < XN4)               { src = (const float4*)x;  dst = xh;            off = i; }
    else if (i < XN4 + WN4)    { src = (const float4*)Wq; dst = wh;            off = i - XN4; }
    else if (i < XN4 + 2*WN4)  { src = (const float4*)Wk; dst = wh + 4*WN4;    off = i - XN4 - WN4; }
    else if (i < XN4 + 3*WN4)  { src = (const float4*)Wv; dst = wh + 8*WN4;    off = i - XN4 - 2*WN4; }
    else                       { src = (const float4*)Wo; dst = woh;           off = i - XN4 - 3*WN4; }
    float4 v = src[off];
    __half2 h0 = __floats2half2_rn(v.x, v.y);
    __half2 h1 = __floats2half2_rn(v.z, v.w);
    ((__half2*)dst)[off * 2]     = h0;
    ((__half2*)dst)[off * 2 + 1] = h1;
}

// ---------------------------------------------------------------------------
// Band attention (R12 structure): tf32 MMA scores + shuffle softmax +
// shfl-broadcast fp32 AV. Output stored fp16 to g_atth (out-proj input).
// smem: Q 64x68 | K 128x68 (aliased as S 64x136) | V 127x68   (f32 words)
// ---------------------------------------------------------------------------
#define QS 68
#define SS 136
#define KV_STRIDE 68
#define QKV_LD (3 * DMODEL)
#define ATTN_Q_WORDS (64 * QS)
#define ATTN_K_WORDS (128 * QS)
#define ATTN_V_WORDS (127 * KV_STRIDE)
#define ATTN_SMEM_BYTES ((ATTN_Q_WORDS + ATTN_K_WORDS + ATTN_V_WORDS) * 4)  // 86768

__global__ __launch_bounds__(256, 2) void band_attn_kernel(
    const float* __restrict__ last_k, const float* __restrict__ last_v)
{
    extern __shared__ float smemf[];
    float* sQ = smemf;
    float* sK = smemf + ATTN_Q_WORDS;
    float* sV = sK + ATTN_K_WORDS;

    const int l0 = blockIdx.x * 64;
    const int h  = blockIdx.y;
    const int b  = blockIdx.z;
    const int tid = threadIdx.x;
    const int wid = tid >> 5;
    const int lane = tid & 31;

    for (int idx = tid; idx < 64 * 16; idx += 256) {
        int r = idx >> 4, c4 = (idx & 15) * 4;
        float4 v = *(const float4*)(g_qkv + (size_t)(b * LSEQ + l0 + r) * QKV_LD + h * DH + c4);
        float* d = sQ + r * QS + c4;
        d[0] = tf32_round(v.x); d[1] = tf32_round(v.y);
        d[2] = tf32_round(v.z); d[3] = tf32_round(v.w);
    }
    for (int idx = tid; idx < 128 * 16; idx += 256) {
        int r = idx >> 4, c4 = (idx & 15) * 4;
        int p = l0 + r;
        float4 v;
        if (p < WWIN - 1) {
            v = *(const float4*)(last_k + (size_t)(p * NH + h) * DH + c4);
        } else {
            int pos = p - (WWIN - 1);
            if (pos < LSEQ)
                v = *(const float4*)(g_qkv + (size_t)(b * LSEQ + pos) * QKV_LD + DMODEL + h * DH + c4);
            else
                v = make_float4(0.f, 0.f, 0.f, 0.f);
        }
        float* d = sK + r * QS + c4;
        d[0] = tf32_round(v.x); d[1] = tf32_round(v.y);
        d[2] = tf32_round(v.z); d[3] = tf32_round(v.w);
    }
    for (int idx = tid; idx < 127 * 16; idx += 256) {
        int r = idx >> 4, c4 = (idx & 15) * 4;
        int p = l0 + r;
        const float* vs;
        if (p < WWIN - 1) {
            vs = last_v + (size_t)(p * NH + h) * DH + c4;
        } else {
            int pos = p - (WWIN - 1);
            vs = g_qkv + (size_t)(b * LSEQ + pos) * QKV_LD + 2 * DMODEL + h * DH + c4;
        }
        *(float4*)(sV + r * KV_STRIDE + c4) = *(const float4*)vs;
    }
    __syncthreads();

    const int mi   = wid >> 1;
    const int half = wid & 1;
    const int a_row = ((lane >> 3) & 1) * 8 + (lane & 7);
    const int a_ko  = (lane >> 4) * 4;
    const int b_row = (lane >> 4) * 8 + (lane & 7);
    const int b_ko  = ((lane >> 3) & 1) * 4;
    const int qr = lane >> 2;
    const int qc = lane & 3;

    float sacc[8][4];
    #pragma unroll
    for (int ni = 0; ni < 8; ni++)
        #pragma unroll
        for (int j = 0; j < 4; j++) sacc[ni][j] = 0.0f;

    {
        const uint32_t qoff = smem_u32(sQ) + (uint32_t)(((mi * 16 + a_row) * QS + a_ko) * 4);
        uint32_t koff[4];
        #pragma unroll
        for (int p4 = 0; p4 < 4; p4++)
            koff[p4] = smem_u32(sK) + (uint32_t)(((half * 64 + p4 * 16 + b_row) * QS + b_ko) * 4);

        #pragma unroll
        for (int k = 0; k < 8; k++) {
            const uint32_t kb = (uint32_t)(k * 32);
            uint32_t af[4];
            ldsm4(af[0], af[1], af[2], af[3], qoff + kb);
            uint32_t bf[8][2];
            #pragma unroll
            for (int p4 = 0; p4 < 4; p4++)
                ldsm4(bf[2*p4][0], bf[2*p4][1], bf[2*p4+1][0], bf[2*p4+1][1], koff[p4] + kb);
            #pragma unroll
            for (int ni = 0; ni < 8; ni++)
                mma_tf32(sacc[ni], af[0], af[1], af[2], af[3], bf[ni][0], bf[ni][1]);
        }
    }
    __syncthreads();

    float* sS = sK;
    #pragma unroll
    for (int ni = 0; ni < 8; ni++) {
        const int r0 = mi * 16 + qr;
        const int c0 = (half * 8 + ni) * 8 + qc * 2;
        sS[r0 * SS + c0]           = sacc[ni][0];
        sS[r0 * SS + c0 + 1]       = sacc[ni][1];
        sS[(r0 + 8) * SS + c0]     = sacc[ni][2];
        sS[(r0 + 8) * SS + c0 + 1] = sacc[ni][3];
    }
    __syncthreads();

    const int q   = tid >> 2;
    const int sub = tid & 3;
    const int qlane = (q & 7) << 2;

    float sreg[16];
    #pragma unroll
    for (int i = 0; i < 16; i++)
        sreg[i] = sS[q * SS + (q + sub + 4 * i)] * 0.125f;

    float m = sreg[0];
    #pragma unroll
    for (int i = 1; i < 16; i++) m = fmaxf(m, sreg[i]);
    m = fmaxf(m, __shfl_xor_sync(0xFFFFFFFFu, m, 1));
    m = fmaxf(m, __shfl_xor_sync(0xFFFFFFFFu, m, 2));
    float ssum = 0.0f;
    #pragma unroll
    for (int i = 0; i < 16; i++) { float e = __expf(sreg[i] - m); sreg[i] = e; ssum += e; }
    ssum += __shfl_xor_sync(0xFFFFFFFFu, ssum, 1);
    ssum += __shfl_xor_sync(0xFFFFFFFFu, ssum, 2);
    const float inv = 1.0f / ssum;
    #pragma unroll
    for (int i = 0; i < 16; i++) sreg[i] *= inv;

    float acc[16];
    #pragma unroll
    for (int j = 0; j < 16; j++) acc[j] = 0.0f;

    #pragma unroll
    for (int i = 0; i < 16; i++) {
        #pragma unroll
        for (int j = 0; j < 4; j++) {
            const int w = i * 4 + j;
            const float p = __shfl_sync(0xFFFFFFFFu, sreg[i], qlane + j);
            const float* vr = sV + (q + w) * KV_STRIDE + sub * 16;
            #pragma unroll
            for (int c4 = 0; c4 < 16; c4 += 4) {
                float4 vv = *(const float4*)(vr + c4);
                acc[c4 + 0] += p * vv.x; acc[c4 + 1] += p * vv.y;
                acc[c4 + 2] += p * vv.z; acc[c4 + 3] += p * vv.w;
            }
        }
    }

    // store fp16 (feeds the out-projection GEMM)
    __half* outp = g_atth + (size_t)(b * LSEQ + l0 + q) * DMODEL + h * DH + sub * 16;
    #pragma unroll
    for (int c4 = 0; c4 < 16; c4 += 4) {
        *(__half2*)(outp + c4)     = __floats2half2_rn(acc[c4],     acc[c4 + 1]);
        *(__half2*)(outp + c4 + 2) = __floats2half2_rn(acc[c4 + 2], acc[c4 + 3]);
    }
}

// ---------------------------------------------------------------------------
// Launch
// ---------------------------------------------------------------------------
extern "C" void kernel_launch(void* const* d_in, const int* in_sizes, int n_in,
                              void* d_out, int out_size)
{
    const float* x      = (const float*)d_in[0];
    const float* Wq     = (const float*)d_in[1];
    const float* Wk     = (const float*)d_in[2];
    const float* Wv     = (const float*)d_in[3];
    const float* Wo     = (const float*)d_in[4];
    const float* last_k = (const float*)d_in[5];
    const float* last_v = (const float*)d_in[6];
    float* out = (float*)d_out;

    __half *pxh, *pwh, *pwoh, *path;
    float *pqkv;
    cudaGetSymbolAddress((void**)&pxh,  g_xh);
    cudaGetSymbolAddress((void**)&pwh,  g_wh);
    cudaGetSymbolAddress((void**)&pwoh, g_woh);
    cudaGetSymbolAddress((void**)&path, g_atth);
    cudaGetSymbolAddress((void**)&pqkv, g_qkv);

    cudaFuncSetAttribute(gemm_fp16_kernel, cudaFuncAttributeMaxDynamicSharedMemorySize,
                         GEMM_SMEM_BYTES);
    cudaFuncSetAttribute(band_attn_kernel, cudaFuncAttributeMaxDynamicSharedMemorySize,
                         ATTN_SMEM_BYTES);

    // 1) fused fp16 conversion of all inputs (one launch)
    round_all_kernel<<<(RN4 + 255) / 256, 256>>>(x, Wq, Wk, Wv, Wo, pxh, pwh, pwoh);

    // 2) fused QKV: g_qkv[2048][3072] = xh @ wh^T   (fp16 MMA, f32 accum)
    {
        dim3 g(3 * DMODEL / 128, MTOT / 128);
        gemm_fp16_kernel<<<g, 256, GEMM_SMEM_BYTES>>>(pxh, pwh, pqkv, 3 * DMODEL);
    }

    // 3) band attention (tf32 MMA scores) -> g_atth (fp16)
    {
        dim3 g(LSEQ / 64, NH, BSZ);
        band_attn_kernel<<<g, 256, ATTN_SMEM_BYTES>>>(last_k, last_v);
    }

    // 4) out = atth @ woh^T   (fp16 MMA, f32 accum)
    {
        dim3 g(DMODEL / 128, MTOT / 128);
        gemm_fp16_kernel<<<g, 256, GEMM_SMEM_BYTES>>>(path, pwoh, out, DMODEL);
    }
}